// round 4
// baseline (speedup 1.0000x reference)
#include <cuda_runtime.h>
#include <cuda_bf16.h>
#include <math.h>
#include <stdint.h>

// ---------------------------------------------------------------------------
// Problem constants
// ---------------------------------------------------------------------------
constexpr int BROWS = 2048;   // B
constexpr int CDIM  = 256;    // feature dim (K)
constexpr int MCOLS = 16384;  // B * topk (N total)
constexpr int KBLK  = 128;    // number of label groups (column blocks of 128)
constexpr int GSZ   = 128;    // group size
constexpr float INV_TEMP = 20.0f;
constexpr float EPS = 1e-6f;

// Scratch (static device globals; no allocation allowed)
__device__ __nv_bfloat16 g_Abf[BROWS * CDIM];   // 1 MB
__device__ __nv_bfloat16 g_Bbf[MCOLS * CDIM];   // 8 MB
__device__ float g_smin[BROWS * KBLK];
__device__ float g_smax[BROWS * KBLK];
__device__ float g_loss[BROWS];

__device__ __forceinline__ uint32_t smem_u32(const void* p) {
    uint32_t a;
    asm("{ .reg .u64 t; cvta.to.shared.u64 t, %1; cvt.u32.u64 %0, t; }"
        : "=r"(a) : "l"(p));
    return a;
}

// ---------------------------------------------------------------------------
// Kernel 0: fp32 -> bf16 conversion (which: 0 -> g_Abf, 1 -> g_Bbf)
// ---------------------------------------------------------------------------
__global__ void convert_bf16_kernel(const float* __restrict__ src, int which, int n8) {
    int i = blockIdx.x * blockDim.x + threadIdx.x;
    if (i >= n8) return;
    __nv_bfloat16* dst = which ? g_Bbf : g_Abf;
    const float4* s = reinterpret_cast<const float4*>(src);
    float4 a = s[2 * i], b = s[2 * i + 1];
    __nv_bfloat162 p0 = __floats2bfloat162_rn(a.x, a.y);
    __nv_bfloat162 p1 = __floats2bfloat162_rn(a.z, a.w);
    __nv_bfloat162 p2 = __floats2bfloat162_rn(b.x, b.y);
    __nv_bfloat162 p3 = __floats2bfloat162_rn(b.z, b.w);
    uint4 o;
    o.x = *reinterpret_cast<uint32_t*>(&p0);
    o.y = *reinterpret_cast<uint32_t*>(&p1);
    o.z = *reinterpret_cast<uint32_t*>(&p2);
    o.w = *reinterpret_cast<uint32_t*>(&p3);
    reinterpret_cast<uint4*>(dst)[i] = o;
}

// ---------------------------------------------------------------------------
// Kernel 1: bf16 mma.sync GEMM tile (M=128, N=128, K=256) + fused min/max.
// grid = (KBLK=128, 16), block = 256 threads (8 warps: 2 M x 4 N).
// SMEM: double-buffered A/B chunks of K=64, XOR-swizzled rows of 128B.
//   Abuf0 @ 0, Abuf1 @ 16384, Bbuf0 @ 32768, Bbuf1 @ 49152  (total 64 KB)
// ---------------------------------------------------------------------------
constexpr int SMEM_TOTAL = 65536;

// swizzled byte offset for (row r, 16B-chunk c) within a 128-row x 128B tile
__device__ __forceinline__ uint32_t sw_off(int r, int c) {
    return (uint32_t)r * 128u + (uint32_t)((c ^ (r & 7)) << 4);
}

__device__ __forceinline__ void load_tile_async(const __nv_bfloat16* g, uint32_t sbase,
                                                int kt, int tid) {
#pragma unroll
    for (int i = 0; i < 4; i++) {
        int idx = tid + i * 256;       // 0..1023
        int r = idx >> 3;              // 0..127
        int c = idx & 7;               // 16B chunk within row
        uint32_t saddr = sbase + sw_off(r, c);
        const void* gptr = g + (size_t)r * CDIM + kt * 64 + c * 8;
        asm volatile("cp.async.cg.shared.global [%0], [%1], 16;"
                     :: "r"(saddr), "l"(gptr) : "memory");
    }
}

__global__ __launch_bounds__(256, 2)
void gemm_mma_kernel() {
    extern __shared__ __align__(128) char smem[];
    const uint32_t sb = smem_u32(smem);
    const int tid = threadIdx.x;
    const int wid = tid >> 5;
    const int lid = tid & 31;
    const int warp_m = wid >> 2;   // 0..1 -> 64 rows
    const int warp_n = wid & 3;    // 0..3 -> 32 cols
    const int rowBase = blockIdx.y * 128;
    const int colBase = blockIdx.x * 128;

    const __nv_bfloat16* Ag = g_Abf + (size_t)rowBase * CDIM;
    const __nv_bfloat16* Bg = g_Bbf + (size_t)colBase * CDIM;

    const uint32_t aOff[2] = {sb + 0u, sb + 16384u};
    const uint32_t bOff[2] = {sb + 32768u, sb + 49152u};

    float acc[4][4][4];
#pragma unroll
    for (int mi = 0; mi < 4; mi++)
#pragma unroll
        for (int nj = 0; nj < 4; nj++)
#pragma unroll
            for (int t = 0; t < 4; t++) acc[mi][nj][t] = 0.0f;

    // prologue: chunk 0 into buffer 0
    load_tile_async(Ag, aOff[0], 0, tid);
    load_tile_async(Bg, bOff[0], 0, tid);
    asm volatile("cp.async.commit_group;" ::: "memory");

#pragma unroll
    for (int kt = 0; kt < 4; kt++) {
        if (kt < 3) {
            load_tile_async(Ag, aOff[(kt + 1) & 1], kt + 1, tid);
            load_tile_async(Bg, bOff[(kt + 1) & 1], kt + 1, tid);
            asm volatile("cp.async.commit_group;" ::: "memory");
            asm volatile("cp.async.wait_group 1;" ::: "memory");
        } else {
            asm volatile("cp.async.wait_group 0;" ::: "memory");
        }
        __syncthreads();

        const uint32_t aS = aOff[kt & 1];
        const uint32_t bS = bOff[kt & 1];

#pragma unroll
        for (int kk = 0; kk < 4; kk++) {   // 4 k16-steps within the K=64 chunk
            // A fragments: 16x16 per mi
            uint32_t a[4][4];
#pragma unroll
            for (int mi = 0; mi < 4; mi++) {
                int r = warp_m * 64 + mi * 16 + (lid & 15);
                int c = 2 * kk + (lid >> 4);
                uint32_t addr = aS + sw_off(r, c);
                asm volatile("ldmatrix.sync.aligned.m8n8.x4.shared.b16 {%0,%1,%2,%3}, [%4];"
                             : "=r"(a[mi][0]), "=r"(a[mi][1]), "=r"(a[mi][2]), "=r"(a[mi][3])
                             : "r"(addr));
            }
            // B fragments: two 16(n)x16(k) loads -> 4 nj fragments
            uint32_t b[4][2];
#pragma unroll
            for (int p = 0; p < 2; p++) {
                int q = lid >> 3;                       // 0..3 quadrant
                int r = warp_n * 32 + p * 16 + ((q & 1) << 3) + (lid & 7);
                int c = 2 * kk + (q >> 1);
                uint32_t addr = bS + sw_off(r, c);
                uint32_t r0, r1, r2, r3;
                asm volatile("ldmatrix.sync.aligned.m8n8.x4.shared.b16 {%0,%1,%2,%3}, [%4];"
                             : "=r"(r0), "=r"(r1), "=r"(r2), "=r"(r3) : "r"(addr));
                b[p * 2 + 0][0] = r0; b[p * 2 + 0][1] = r2;
                b[p * 2 + 1][0] = r1; b[p * 2 + 1][1] = r3;
            }
#pragma unroll
            for (int mi = 0; mi < 4; mi++)
#pragma unroll
                for (int nj = 0; nj < 4; nj++) {
                    asm volatile(
                        "mma.sync.aligned.m16n8k16.row.col.f32.bf16.bf16.f32 "
                        "{%0,%1,%2,%3}, {%4,%5,%6,%7}, {%8,%9}, {%0,%1,%2,%3};"
                        : "+f"(acc[mi][nj][0]), "+f"(acc[mi][nj][1]),
                          "+f"(acc[mi][nj][2]), "+f"(acc[mi][nj][3])
                        : "r"(a[mi][0]), "r"(a[mi][1]), "r"(a[mi][2]), "r"(a[mi][3]),
                          "r"(b[nj][0]), "r"(b[nj][1]));
                }
        }
        __syncthreads();
    }

    // ---------------- fused min/max epilogue ----------------
    // d-fragment rows: mi*16 + lid/4 (regs 0,1) and +8 (regs 2,3); cols vary by lane%4 + nj.
    float* sMin = reinterpret_cast<float*>(smem);          // [4][128]
    float* sMax = reinterpret_cast<float*>(smem + 2048);   // [4][128]

#pragma unroll
    for (int mi = 0; mi < 4; mi++) {
        float mnl = 1e30f, mxl = -1e30f, mnh = 1e30f, mxh = -1e30f;
#pragma unroll
        for (int nj = 0; nj < 4; nj++) {
            mnl = fminf(mnl, fminf(acc[mi][nj][0], acc[mi][nj][1]));
            mxl = fmaxf(mxl, fmaxf(acc[mi][nj][0], acc[mi][nj][1]));
            mnh = fminf(mnh, fminf(acc[mi][nj][2], acc[mi][nj][3]));
            mxh = fmaxf(mxh, fmaxf(acc[mi][nj][2], acc[mi][nj][3]));
        }
#pragma unroll
        for (int off = 1; off <= 2; off <<= 1) {
            mnl = fminf(mnl, __shfl_xor_sync(0xffffffffu, mnl, off));
            mxl = fmaxf(mxl, __shfl_xor_sync(0xffffffffu, mxl, off));
            mnh = fminf(mnh, __shfl_xor_sync(0xffffffffu, mnh, off));
            mxh = fmaxf(mxh, __shfl_xor_sync(0xffffffffu, mxh, off));
        }
        if ((lid & 3) == 0) {
            int rl = warp_m * 64 + mi * 16 + (lid >> 2);
            sMin[warp_n * 128 + rl] = mnl;
            sMax[warp_n * 128 + rl] = mxl;
            sMin[warp_n * 128 + rl + 8] = mnh;
            sMax[warp_n * 128 + rl + 8] = mxh;
        }
    }
    __syncthreads();

    if (tid < 128) {
        float mn = sMin[tid], mx = sMax[tid];
#pragma unroll
        for (int w = 1; w < 4; w++) {
            mn = fminf(mn, sMin[w * 128 + tid]);
            mx = fmaxf(mx, sMax[w * 128 + tid]);
        }
        g_smin[(rowBase + tid) * KBLK + blockIdx.x] = mn;
        g_smax[(rowBase + tid) * KBLK + blockIdx.x] = mx;
    }
}

// ---------------------------------------------------------------------------
// Kernel 2: per-row loss. One warp per row.
// ---------------------------------------------------------------------------
__global__ void loss_kernel(const int* __restrict__ labels,
                            const int* __restrict__ labels_s) {
    int warp = (blockIdx.x * blockDim.x + threadIdx.x) >> 5;
    int lane = threadIdx.x & 31;
    if (warp >= BROWS) return;

    int lab = labels[warp];
    float pos = 0.0f, neg = 0.0f;
#pragma unroll
    for (int k = lane; k < KBLK; k += 32) {
        int gl = labels_s[k * GSZ];
        if (gl == lab) {
            pos += expf(g_smin[warp * KBLK + k] * INV_TEMP);
        } else {
            neg += expf(g_smax[warp * KBLK + k] * INV_TEMP);
        }
    }
#pragma unroll
    for (int off = 16; off > 0; off >>= 1) {
        pos += __shfl_xor_sync(0xffffffffu, pos, off);
        neg += __shfl_xor_sync(0xffffffffu, neg, off);
    }
    if (lane == 0) {
        g_loss[warp] = -logf(pos / (pos + neg + EPS) + EPS);
    }
}

// ---------------------------------------------------------------------------
// Kernel 3: deterministic mean -> scalar output.
// ---------------------------------------------------------------------------
__global__ void mean_kernel(float* __restrict__ out) {
    __shared__ float s[256];
    int t = threadIdx.x;
    float v = 0.0f;
#pragma unroll
    for (int i = 0; i < BROWS / 256; i++) v += g_loss[t + i * 256];
    s[t] = v;
    __syncthreads();
    for (int st = 128; st > 0; st >>= 1) {
        if (t < st) s[t] += s[t + st];
        __syncthreads();
    }
    if (t == 0) out[0] = s[0] / (float)BROWS;
}

// ---------------------------------------------------------------------------
extern "C" void kernel_launch(void* const* d_in, const int* in_sizes, int n_in,
                              void* d_out, int out_size) {
    const float* feats    = (const float*)d_in[0];   // [2048, 256]
    const float* feats_s  = (const float*)d_in[1];   // [16384, 256]
    const int*   labels   = (const int*)d_in[2];
    const int*   labels_s = (const int*)d_in[3];
    float* out = (float*)d_out;

    cudaFuncSetAttribute(gemm_mma_kernel,
                         cudaFuncAttributeMaxDynamicSharedMemorySize, SMEM_TOTAL);

    int n8a = BROWS * CDIM / 8;
    convert_bf16_kernel<<<(n8a + 255) / 256, 256>>>(feats, 0, n8a);
    int n8b = MCOLS * CDIM / 8;
    convert_bf16_kernel<<<(n8b + 255) / 256, 256>>>(feats_s, 1, n8b);

    dim3 grid(KBLK, BROWS / 128);   // 128 x 16 tiles
    gemm_mma_kernel<<<grid, 256, SMEM_TOTAL>>>();

    loss_kernel<<<BROWS / 8, 256>>>(labels, labels_s);
    mean_kernel<<<1, 256>>>(out);
}

// round 5
// speedup vs baseline: 1.4979x; 1.4979x over previous
#include <cuda_runtime.h>
#include <cuda_bf16.h>
#include <math.h>
#include <stdint.h>

// ---------------------------------------------------------------------------
// Problem constants
// ---------------------------------------------------------------------------
constexpr int BROWS = 2048;   // B
constexpr int CDIM  = 256;    // feature dim (K)
constexpr int MCOLS = 16384;  // B * topk (N total)
constexpr int KBLK  = 128;    // number of label groups (column blocks of 128)
constexpr int GSZ   = 128;    // group size
constexpr float INV_TEMP = 20.0f;
constexpr float EPS = 1e-6f;

// Scratch (static device globals; no allocation allowed)
__device__ __nv_bfloat16 g_Abf[BROWS * CDIM];   // 1 MB
__device__ __nv_bfloat16 g_Bbf[MCOLS * CDIM];   // 8 MB
__device__ float g_smin[BROWS * KBLK];
__device__ float g_smax[BROWS * KBLK];
__device__ float g_loss[BROWS];

__device__ __forceinline__ uint32_t smem_u32(const void* p) {
    uint32_t a;
    asm("{ .reg .u64 t; cvta.to.shared.u64 t, %1; cvt.u32.u64 %0, t; }"
        : "=r"(a) : "l"(p));
    return a;
}

// ---------------------------------------------------------------------------
// Kernel 0: fp32 -> bf16 conversion (which: 0 -> g_Abf, 1 -> g_Bbf)
// ---------------------------------------------------------------------------
__global__ void convert_bf16_kernel(const float* __restrict__ src, int which, int n8) {
    int i = blockIdx.x * blockDim.x + threadIdx.x;
    if (i >= n8) return;
    __nv_bfloat16* dst = which ? g_Bbf : g_Abf;
    const float4* s = reinterpret_cast<const float4*>(src);
    float4 a = s[2 * i], b = s[2 * i + 1];
    __nv_bfloat162 p0 = __floats2bfloat162_rn(a.x, a.y);
    __nv_bfloat162 p1 = __floats2bfloat162_rn(a.z, a.w);
    __nv_bfloat162 p2 = __floats2bfloat162_rn(b.x, b.y);
    __nv_bfloat162 p3 = __floats2bfloat162_rn(b.z, b.w);
    uint4 o;
    o.x = *reinterpret_cast<uint32_t*>(&p0);
    o.y = *reinterpret_cast<uint32_t*>(&p1);
    o.z = *reinterpret_cast<uint32_t*>(&p2);
    o.w = *reinterpret_cast<uint32_t*>(&p3);
    reinterpret_cast<uint4*>(dst)[i] = o;
}

// ---------------------------------------------------------------------------
// Kernel 1: bf16 mma.sync GEMM tile (M=128, N=128, K=256) + fused min/max.
// grid = (KBLK=128, 16), block = 256 threads (8 warps: 2 M x 4 N).
// SMEM: double-buffered A/B chunks of K=64, XOR-swizzled rows of 128B.
//   Abuf0 @ 0, Abuf1 @ 16384, Bbuf0 @ 32768, Bbuf1 @ 49152  (total 64 KB)
// ---------------------------------------------------------------------------
constexpr int SMEM_TOTAL = 65536;

// swizzled byte offset for (row r, 16B-chunk c) within a 128-row x 128B tile
__device__ __forceinline__ uint32_t sw_off(int r, int c) {
    return (uint32_t)r * 128u + (uint32_t)((c ^ (r & 7)) << 4);
}

__device__ __forceinline__ void load_tile_async(const __nv_bfloat16* g, uint32_t sbase,
                                                int kt, int tid) {
#pragma unroll
    for (int i = 0; i < 4; i++) {
        int idx = tid + i * 256;       // 0..1023
        int r = idx >> 3;              // 0..127
        int c = idx & 7;               // 16B chunk within row
        uint32_t saddr = sbase + sw_off(r, c);
        const void* gptr = g + (size_t)r * CDIM + kt * 64 + c * 8;
        asm volatile("cp.async.cg.shared.global [%0], [%1], 16;"
                     :: "r"(saddr), "l"(gptr) : "memory");
    }
}

__global__ __launch_bounds__(256, 2)
void gemm_mma_kernel() {
    extern __shared__ __align__(128) char smem[];
    const uint32_t sb = smem_u32(smem);
    const int tid = threadIdx.x;
    const int wid = tid >> 5;
    const int lid = tid & 31;
    const int warp_m = wid >> 2;   // 0..1 -> 64 rows
    const int warp_n = wid & 3;    // 0..3 -> 32 cols
    const int rowBase = blockIdx.y * 128;
    const int colBase = blockIdx.x * 128;

    const __nv_bfloat16* Ag = g_Abf + (size_t)rowBase * CDIM;
    const __nv_bfloat16* Bg = g_Bbf + (size_t)colBase * CDIM;

    const uint32_t aOff[2] = {sb + 0u, sb + 16384u};
    const uint32_t bOff[2] = {sb + 32768u, sb + 49152u};

    float acc[4][4][4];
#pragma unroll
    for (int mi = 0; mi < 4; mi++)
#pragma unroll
        for (int nj = 0; nj < 4; nj++)
#pragma unroll
            for (int t = 0; t < 4; t++) acc[mi][nj][t] = 0.0f;

    // prologue: chunk 0 into buffer 0
    load_tile_async(Ag, aOff[0], 0, tid);
    load_tile_async(Bg, bOff[0], 0, tid);
    asm volatile("cp.async.commit_group;" ::: "memory");

#pragma unroll
    for (int kt = 0; kt < 4; kt++) {
        if (kt < 3) {
            load_tile_async(Ag, aOff[(kt + 1) & 1], kt + 1, tid);
            load_tile_async(Bg, bOff[(kt + 1) & 1], kt + 1, tid);
            asm volatile("cp.async.commit_group;" ::: "memory");
            asm volatile("cp.async.wait_group 1;" ::: "memory");
        } else {
            asm volatile("cp.async.wait_group 0;" ::: "memory");
        }
        __syncthreads();

        const uint32_t aS = aOff[kt & 1];
        const uint32_t bS = bOff[kt & 1];

#pragma unroll
        for (int kk = 0; kk < 4; kk++) {   // 4 k16-steps within the K=64 chunk
            // A fragments: 16x16 per mi
            uint32_t a[4][4];
#pragma unroll
            for (int mi = 0; mi < 4; mi++) {
                int r = warp_m * 64 + mi * 16 + (lid & 15);
                int c = 2 * kk + (lid >> 4);
                uint32_t addr = aS + sw_off(r, c);
                asm volatile("ldmatrix.sync.aligned.m8n8.x4.shared.b16 {%0,%1,%2,%3}, [%4];"
                             : "=r"(a[mi][0]), "=r"(a[mi][1]), "=r"(a[mi][2]), "=r"(a[mi][3])
                             : "r"(addr));
            }
            // B fragments: two 16(n)x16(k) loads -> 4 nj fragments
            uint32_t b[4][2];
#pragma unroll
            for (int p = 0; p < 2; p++) {
                int q = lid >> 3;                       // 0..3 quadrant
                int r = warp_n * 32 + p * 16 + ((q & 1) << 3) + (lid & 7);
                int c = 2 * kk + (q >> 1);
                uint32_t addr = bS + sw_off(r, c);
                uint32_t r0, r1, r2, r3;
                asm volatile("ldmatrix.sync.aligned.m8n8.x4.shared.b16 {%0,%1,%2,%3}, [%4];"
                             : "=r"(r0), "=r"(r1), "=r"(r2), "=r"(r3) : "r"(addr));
                b[p * 2 + 0][0] = r0; b[p * 2 + 0][1] = r2;
                b[p * 2 + 1][0] = r1; b[p * 2 + 1][1] = r3;
            }
#pragma unroll
            for (int mi = 0; mi < 4; mi++)
#pragma unroll
                for (int nj = 0; nj < 4; nj++) {
                    asm volatile(
                        "mma.sync.aligned.m16n8k16.row.col.f32.bf16.bf16.f32 "
                        "{%0,%1,%2,%3}, {%4,%5,%6,%7}, {%8,%9}, {%0,%1,%2,%3};"
                        : "+f"(acc[mi][nj][0]), "+f"(acc[mi][nj][1]),
                          "+f"(acc[mi][nj][2]), "+f"(acc[mi][nj][3])
                        : "r"(a[mi][0]), "r"(a[mi][1]), "r"(a[mi][2]), "r"(a[mi][3]),
                          "r"(b[nj][0]), "r"(b[nj][1]));
                }
        }
        __syncthreads();
    }

    // ---------------- fused min/max epilogue ----------------
    // d-fragment rows: mi*16 + lid/4 (regs 0,1) and +8 (regs 2,3); cols vary by lane%4 + nj.
    float* sMin = reinterpret_cast<float*>(smem);          // [4][128]
    float* sMax = reinterpret_cast<float*>(smem + 2048);   // [4][128]

#pragma unroll
    for (int mi = 0; mi < 4; mi++) {
        float mnl = 1e30f, mxl = -1e30f, mnh = 1e30f, mxh = -1e30f;
#pragma unroll
        for (int nj = 0; nj < 4; nj++) {
            mnl = fminf(mnl, fminf(acc[mi][nj][0], acc[mi][nj][1]));
            mxl = fmaxf(mxl, fmaxf(acc[mi][nj][0], acc[mi][nj][1]));
            mnh = fminf(mnh, fminf(acc[mi][nj][2], acc[mi][nj][3]));
            mxh = fmaxf(mxh, fmaxf(acc[mi][nj][2], acc[mi][nj][3]));
        }
#pragma unroll
        for (int off = 1; off <= 2; off <<= 1) {
            mnl = fminf(mnl, __shfl_xor_sync(0xffffffffu, mnl, off));
            mxl = fmaxf(mxl, __shfl_xor_sync(0xffffffffu, mxl, off));
            mnh = fminf(mnh, __shfl_xor_sync(0xffffffffu, mnh, off));
            mxh = fmaxf(mxh, __shfl_xor_sync(0xffffffffu, mxh, off));
        }
        if ((lid & 3) == 0) {
            int rl = warp_m * 64 + mi * 16 + (lid >> 2);
            sMin[warp_n * 128 + rl] = mnl;
            sMax[warp_n * 128 + rl] = mxl;
            sMin[warp_n * 128 + rl + 8] = mnh;
            sMax[warp_n * 128 + rl + 8] = mxh;
        }
    }
    __syncthreads();

    if (tid < 128) {
        float mn = sMin[tid], mx = sMax[tid];
#pragma unroll
        for (int w = 1; w < 4; w++) {
            mn = fminf(mn, sMin[w * 128 + tid]);
            mx = fmaxf(mx, sMax[w * 128 + tid]);
        }
        g_smin[(rowBase + tid) * KBLK + blockIdx.x] = mn;
        g_smax[(rowBase + tid) * KBLK + blockIdx.x] = mx;
    }
}

// ---------------------------------------------------------------------------
// Kernel 2: per-row loss. One warp per row.
// ---------------------------------------------------------------------------
__global__ void loss_kernel(const int* __restrict__ labels,
                            const int* __restrict__ labels_s) {
    int warp = (blockIdx.x * blockDim.x + threadIdx.x) >> 5;
    int lane = threadIdx.x & 31;
    if (warp >= BROWS) return;

    int lab = labels[warp];
    float pos = 0.0f, neg = 0.0f;
#pragma unroll
    for (int k = lane; k < KBLK; k += 32) {
        int gl = labels_s[k * GSZ];
        if (gl == lab) {
            pos += expf(g_smin[warp * KBLK + k] * INV_TEMP);
        } else {
            neg += expf(g_smax[warp * KBLK + k] * INV_TEMP);
        }
    }
#pragma unroll
    for (int off = 16; off > 0; off >>= 1) {
        pos += __shfl_xor_sync(0xffffffffu, pos, off);
        neg += __shfl_xor_sync(0xffffffffu, neg, off);
    }
    if (lane == 0) {
        g_loss[warp] = -logf(pos / (pos + neg + EPS) + EPS);
    }
}

// ---------------------------------------------------------------------------
// Kernel 3: deterministic mean -> scalar output.
// ---------------------------------------------------------------------------
__global__ void mean_kernel(float* __restrict__ out) {
    __shared__ float s[256];
    int t = threadIdx.x;
    float v = 0.0f;
#pragma unroll
    for (int i = 0; i < BROWS / 256; i++) v += g_loss[t + i * 256];
    s[t] = v;
    __syncthreads();
    for (int st = 128; st > 0; st >>= 1) {
        if (t < st) s[t] += s[t + st];
        __syncthreads();
    }
    if (t == 0) out[0] = s[0] / (float)BROWS;
}

// ---------------------------------------------------------------------------
extern "C" void kernel_launch(void* const* d_in, const int* in_sizes, int n_in,
                              void* d_out, int out_size) {
    const float* feats    = (const float*)d_in[0];   // [2048, 256]
    const float* feats_s  = (const float*)d_in[1];   // [16384, 256]
    const int*   labels   = (const int*)d_in[2];
    const int*   labels_s = (const int*)d_in[3];
    float* out = (float*)d_out;

    cudaFuncSetAttribute(gemm_mma_kernel,
                         cudaFuncAttributeMaxDynamicSharedMemorySize, SMEM_TOTAL);

    int n8a = BROWS * CDIM / 8;
    convert_bf16_kernel<<<(n8a + 255) / 256, 256>>>(feats, 0, n8a);
    int n8b = MCOLS * CDIM / 8;
    convert_bf16_kernel<<<(n8b + 255) / 256, 256>>>(feats_s, 1, n8b);

    dim3 grid(KBLK, BROWS / 128);   // 128 x 16 tiles
    gemm_mma_kernel<<<grid, 256, SMEM_TOTAL>>>();

    loss_kernel<<<BROWS / 8, 256>>>(labels, labels_s);
    mean_kernel<<<1, 256>>>(out);
}